// round 1
// baseline (speedup 1.0000x reference)
#include <cuda_runtime.h>
#include <cuda_bf16.h>

// Shapes fixed by the problem definition.
#define BATCH 256
#define HWPIX 1024            // 32*32
#define CHAN  256
#define NPART 4
#define PSIZE 64              // BATCH / NPART
#define EPSV  0.001f

// Scratch (allocation-free rule): device globals.
__device__ float g_sum[NPART][CHAN];
__device__ float g_sq[NPART][CHAN];
__device__ float g_scale[NPART][CHAN];
__device__ float g_bias[NPART][CHAN];
__device__ int   g_part[BATCH];

// ---------------------------------------------------------------------------
// Kernel 1: build partition map from perm, zero accumulators.
// out[j] uses partition of j = (position of j in perm) / PSIZE.
// ---------------------------------------------------------------------------
__global__ void k_prep(const int* __restrict__ perm) {
    int t = threadIdx.x;             // 256 threads
    g_part[perm[t]] = t / PSIZE;
    // zero 2 * NPART * CHAN = 2048 floats
    float* s = &g_sum[0][0];
    float* q = &g_sq[0][0];
    for (int i = t; i < NPART * CHAN; i += 256) {
        s[i] = 0.0f;
        q[i] = 0.0f;
    }
}

// ---------------------------------------------------------------------------
// Kernel 2: per-(partition, channel) sum and sum-of-squares.
// grid = (BATCH, 4 pixel-chunks), block = 256 threads.
// Thread layout: c4 = tid & 63 (channel quad), psub = tid >> 6 (pixel subgroup).
// Each thread float4-loads 64 pixel rows -> register accumulate ->
// shared reduction across 4 psub groups -> 2 atomicAdds per channel.
// ---------------------------------------------------------------------------
__global__ void k_stats(const float4* __restrict__ x) {
    const int b     = blockIdx.x;
    const int chunk = blockIdx.y;           // 4 chunks of 256 pixels each
    const int t     = threadIdx.x;
    const int c4    = t & 63;
    const int psub  = t >> 6;

    const float4* base = x + ((size_t)b * HWPIX + (size_t)chunk * 256) * (CHAN / 4) + c4;

    float4 s = make_float4(0.f, 0.f, 0.f, 0.f);
    float4 q = make_float4(0.f, 0.f, 0.f, 0.f);
    #pragma unroll 8
    for (int i = 0; i < 64; i++) {
        float4 v = base[(size_t)(i * 4 + psub) * (CHAN / 4)];
        s.x += v.x; s.y += v.y; s.z += v.z; s.w += v.w;
        q.x += v.x * v.x; q.y += v.y * v.y; q.z += v.z * v.z; q.w += v.w * v.w;
    }

    __shared__ float ssum[4][CHAN];
    __shared__ float ssq[4][CHAN];
    const int cbase = c4 * 4;
    ssum[psub][cbase + 0] = s.x; ssum[psub][cbase + 1] = s.y;
    ssum[psub][cbase + 2] = s.z; ssum[psub][cbase + 3] = s.w;
    ssq[psub][cbase + 0]  = q.x; ssq[psub][cbase + 1]  = q.y;
    ssq[psub][cbase + 2]  = q.z; ssq[psub][cbase + 3]  = q.w;
    __syncthreads();

    // one thread per channel reduces 4 subgroups and pushes global atomics
    const int p = g_part[b];
    float ts = ssum[0][t] + ssum[1][t] + ssum[2][t] + ssum[3][t];
    float tq = ssq[0][t]  + ssq[1][t]  + ssq[2][t]  + ssq[3][t];
    atomicAdd(&g_sum[p][t], ts);
    atomicAdd(&g_sq[p][t], tq);
}

// ---------------------------------------------------------------------------
// Kernel 3: fold stats into fused scale/bias.  grid=(NPART), block=(CHAN).
// ---------------------------------------------------------------------------
__global__ void k_finalize(const float* __restrict__ gamma,
                           const float* __restrict__ beta) {
    const int p = blockIdx.x;
    const int c = threadIdx.x;
    const float invN = 1.0f / (float)(PSIZE * HWPIX);
    float mean = g_sum[p][c] * invN;
    float var  = g_sq[p][c] * invN - mean * mean;
    float sc   = gamma[p * CHAN + c] * rsqrtf(var + EPSV);
    g_scale[p][c] = sc;
    g_bias[p][c]  = beta[p * CHAN + c] - mean * sc;
}

// ---------------------------------------------------------------------------
// Kernel 4: normalize.  grid = (BATCH, 16 pixel-chunks), block = 256.
// Each thread owns a fixed channel quad; scale/bias live in registers.
// float4 in, float4 out -> pure LDG.128/FFMA/STG.128 stream.
// ---------------------------------------------------------------------------
__global__ void k_norm(const float4* __restrict__ x, float4* __restrict__ out) {
    const int b    = blockIdx.x;
    const int t    = threadIdx.x;
    const int c4   = t & 63;
    const int psub = t >> 6;
    const int p    = g_part[b];

    const float4 sc = ((const float4*)g_scale)[p * (CHAN / 4) + c4];
    const float4 bi = ((const float4*)g_bias)[p * (CHAN / 4) + c4];

    const size_t base = (size_t)b * HWPIX * (CHAN / 4)
                      + (size_t)blockIdx.y * 64 * (CHAN / 4)
                      + c4;
    #pragma unroll
    for (int i = 0; i < 16; i++) {
        size_t idx = base + (size_t)(i * 4 + psub) * (CHAN / 4);
        float4 v = x[idx];
        v.x = v.x * sc.x + bi.x;
        v.y = v.y * sc.y + bi.y;
        v.z = v.z * sc.z + bi.z;
        v.w = v.w * sc.w + bi.w;
        out[idx] = v;
    }
}

// ---------------------------------------------------------------------------
extern "C" void kernel_launch(void* const* d_in, const int* in_sizes, int n_in,
                              void* d_out, int out_size) {
    const float* x     = (const float*)d_in[0];
    const float* gamma = (const float*)d_in[1];
    const float* beta  = (const float*)d_in[2];
    const int*   perm  = (const int*)d_in[3];
    float* out = (float*)d_out;

    k_prep<<<1, 256>>>(perm);
    k_stats<<<dim3(BATCH, 4), 256>>>((const float4*)x);
    k_finalize<<<NPART, CHAN>>>(gamma, beta);
    k_norm<<<dim3(BATCH, 16), 256>>>((const float4*)x, (float4*)out);
}